// round 15
// baseline (speedup 1.0000x reference)
#include <cuda_runtime.h>
#include <cuda_fp16.h>

// AdditiveAttention: out[b,i,:] = softmax_j( sum_h tanh(qp+kp)*wv, mask j<vl ) @ values
// B=8, LQ=128, LK=1024, D=512, H=256, DV=512

static constexpr int B_  = 8;
static constexpr int LQ_ = 128;
static constexpr int LK_ = 1024;
static constexpr int D_  = 512;
static constexpr int H_  = 256;
static constexpr int H2_ = 128;
static constexpr int DV_ = 512;
static constexpr int QT  = 8;
static constexpr int SPL = 4;      // key splits
static constexpr int TJS = 256;    // keys per split
static constexpr int NTH = 256;    // 8 warps
static constexpr int EP  = 12;     // padded s_e row
static constexpr int KH  = 8;      // h2 rows per k-chunk
static constexpr int NCH = H2_ / KH;  // 16 chunks
static constexpr int NQT = B_ * (LQ_ / QT);   // 128 q-tiles
static constexpr int AROWS = B_ * LQ_ + B_ * LK_;
static constexpr int NST = 4;      // proj pipeline stages

__device__ __half  g_Ah[AROWS * D_];         // fp16 copy of [queries; keys]
__device__ __half  g_Whq[D_ * H_];           // fp16 Wq
__device__ __half  g_Whk[D_ * H_];           // fp16 Wk
__device__ __half  g_qh[B_ * LQ_ * H_];      // q proj [row][h] fp16
__device__ __half2 g_kT[B_ * H2_ * LK_];     // k proj transposed [b][h2][j]
__device__ float   g_pAV[NQT][SPL][QT][DV_]; // partial e*V
__device__ float   g_psum[NQT][SPL][QT];     // partial sum(e)
__device__ unsigned g_tick[NQT];             // split completion tickets

// ---------------- helpers ----------------
__device__ __forceinline__ void cp16(void* dst, const void* src) {
    unsigned d = (unsigned)__cvta_generic_to_shared(dst);
    asm volatile("cp.async.cg.shared.global [%0], [%1], 16;" :: "r"(d), "l"(src));
}
__device__ __forceinline__ void ldsm_x4(unsigned* r, const void* p) {
    unsigned addr = (unsigned)__cvta_generic_to_shared(p);
    asm volatile("ldmatrix.sync.aligned.m8n8.x4.shared.b16 {%0,%1,%2,%3}, [%4];"
                 : "=r"(r[0]), "=r"(r[1]), "=r"(r[2]), "=r"(r[3]) : "r"(addr));
}
__device__ __forceinline__ void ldsm_x4_t(unsigned* r, const void* p) {
    unsigned addr = (unsigned)__cvta_generic_to_shared(p);
    asm volatile("ldmatrix.sync.aligned.m8n8.x4.trans.shared.b16 {%0,%1,%2,%3}, [%4];"
                 : "=r"(r[0]), "=r"(r[1]), "=r"(r[2]), "=r"(r[3]) : "r"(addr));
}
__device__ __forceinline__ void mma_f16(float* c, const unsigned* a, const unsigned* b) {
    asm volatile(
        "mma.sync.aligned.m16n8k16.row.col.f32.f16.f16.f32 "
        "{%0,%1,%2,%3}, {%4,%5,%6,%7}, {%8,%9}, {%0,%1,%2,%3};"
        : "+f"(c[0]), "+f"(c[1]), "+f"(c[2]), "+f"(c[3])
        : "r"(a[0]), "r"(a[1]), "r"(a[2]), "r"(a[3]), "r"(b[0]), "r"(b[1]));
}
__device__ __forceinline__ __half2 htanh2(__half2 x) {
    unsigned xi = *reinterpret_cast<unsigned*>(&x), yi;
    asm("tanh.approx.f16x2 %0, %1;" : "=r"(yi) : "r"(xi));
    return *reinterpret_cast<__half2*>(&yi);
}
__device__ __forceinline__ float warp_sum(float v) {
#pragma unroll
    for (int off = 16; off; off >>= 1) v += __shfl_xor_sync(0xffffffffu, v, off);
    return v;
}

// ---------------- convert inputs to fp16 (+ reset tickets) ----------------
static constexpr int NQ4 = B_ * LQ_ * D_ / 4;
static constexpr int NK4 = B_ * LK_ * D_ / 4;
static constexpr int NW4 = D_ * H_ / 4;
static constexpr int TOT4 = NQ4 + NK4 + 2 * NW4;

__global__ __launch_bounds__(256) void to_half(const float* __restrict__ q,
                                               const float* __restrict__ k,
                                               const float* __restrict__ wq,
                                               const float* __restrict__ wk) {
    if (blockIdx.x == 0 && threadIdx.x < NQT) g_tick[threadIdx.x] = 0u;
    for (int i = blockIdx.x * 256 + threadIdx.x; i < TOT4; i += gridDim.x * 256) {
        const float4* src; __half* dst; int off;
        if (i < NQ4)                   { src = (const float4*)q;  dst = g_Ah;                off = i; }
        else if (i < NQ4 + NK4)        { src = (const float4*)k;  dst = g_Ah + (size_t)B_ * LQ_ * D_; off = i - NQ4; }
        else if (i < NQ4 + NK4 + NW4)  { src = (const float4*)wq; dst = g_Whq;              off = i - NQ4 - NK4; }
        else                           { src = (const float4*)wk; dst = g_Whk;              off = i - NQ4 - NK4 - NW4; }
        float4 v = src[off];
        *(__half2*)&dst[(size_t)off * 4]     = __floats2half2_rn(v.x, v.y);
        *(__half2*)&dst[(size_t)off * 4 + 2] = __floats2half2_rn(v.z, v.w);
    }
}

// ---------------- projections: fp16 mma + ldmatrix + 4-stage cp.async ----------------
__global__ __launch_bounds__(128) void proj_mma() {
    __shared__ __half As[NST][64][40];   // 20.5 KB
    __shared__ __half Ws[NST][32][72];   // 18.4 KB

    const bool is_q = (blockIdx.y < 16);
    const int m0 = (is_q ? blockIdx.y : (blockIdx.y - 16)) * 64;
    const int n0 = blockIdx.x * 64;
    const __half* Asrc = g_Ah + (size_t)((is_q ? 0 : B_ * LQ_) + m0) * D_;
    const __half* Wsrc = is_q ? g_Whq : g_Whk;

    const int tid = threadIdx.x, warp = tid >> 5, lane = tid & 31;
    const int wm = (warp & 1) * 32, wn = (warp >> 1) * 32;
    const int g = lane >> 2, tg = lane & 3;

    float c[2][4][4];
#pragma unroll
    for (int mt = 0; mt < 2; mt++)
#pragma unroll
        for (int nt = 0; nt < 4; nt++)
#pragma unroll
            for (int i = 0; i < 4; i++) c[mt][nt][i] = 0.f;

    auto load_stage = [&](int t) {
        const int buf = t & 3, k0 = t * 32;
#pragma unroll
        for (int cc = tid; cc < 256; cc += 128) {
            int row = cc >> 2, col8 = (cc & 3) * 8;
            cp16(&As[buf][row][col8], Asrc + (size_t)row * D_ + k0 + col8);
        }
#pragma unroll
        for (int cc = tid; cc < 256; cc += 128) {
            int row = cc >> 3, col8 = (cc & 7) * 8;
            cp16(&Ws[buf][row][col8], Wsrc + (size_t)(k0 + row) * H_ + n0 + col8);
        }
        asm volatile("cp.async.commit_group;" ::: "memory");
    };

    load_stage(0);
    load_stage(1);
    load_stage(2);
    for (int t = 0; t < 16; t++) {
        // groups t..min(t+2,15) pending; need group t done
        if (t <= 13) {
            asm volatile("cp.async.wait_group 2;" ::: "memory");
        } else if (t == 14) {
            asm volatile("cp.async.wait_group 1;" ::: "memory");
        } else {
            asm volatile("cp.async.wait_group 0;" ::: "memory");
        }
        __syncthreads();                 // one barrier per iter: releases buffer (t-1)%4 too
        if (t + 3 < 16) load_stage(t + 3);
        const int buf = t & 3;
#pragma unroll
        for (int ks = 0; ks < 2; ks++) {
            unsigned a[2][4], bf[2][4];
#pragma unroll
            for (int mt = 0; mt < 2; mt++)
                ldsm_x4(a[mt], &As[buf][wm + mt * 16 + (lane & 15)][ks * 16 + ((lane >> 4) << 3)]);
#pragma unroll
            for (int np = 0; np < 2; np++)
                ldsm_x4_t(bf[np], &Ws[buf][ks * 16 + (lane & 15)][wn + np * 16 + ((lane >> 4) << 3)]);
#pragma unroll
            for (int mt = 0; mt < 2; mt++)
#pragma unroll
                for (int np = 0; np < 2; np++) {
                    mma_f16(c[mt][np * 2],     a[mt], &bf[np][0]);
                    mma_f16(c[mt][np * 2 + 1], a[mt], &bf[np][2]);
                }
        }
    }

#pragma unroll
    for (int mt = 0; mt < 2; mt++)
#pragma unroll
        for (int nt = 0; nt < 4; nt++) {
            int row = m0 + wm + mt * 16 + g;
            int col = n0 + wn + nt * 8 + tg * 2;
            __half2 lo = __floats2half2_rn(c[mt][nt][0], c[mt][nt][1]);
            __half2 hi = __floats2half2_rn(c[mt][nt][2], c[mt][nt][3]);
            if (is_q) {
                *(__half2*)&g_qh[(size_t)row * H_ + col] = lo;
                *(__half2*)&g_qh[(size_t)(row + 8) * H_ + col] = hi;
            } else {
                int b_ = row >> 10, j = row & 1023;
                int h2 = col >> 1;
                g_kT[((size_t)b_ * H2_ + h2) * LK_ + j] = lo;
                g_kT[((size_t)b_ * H2_ + h2) * LK_ + (j + 8)] = hi;
            }
        }
}

// ---------------- split-K partial attention + fused last-CTA reduce ----------------
__global__ __launch_bounds__(NTH, 2) void partial_attn(
    const float* __restrict__ values,
    const float* __restrict__ wv,
    const int* __restrict__ valid_lens,
    float* __restrict__ out) {
    __shared__ float   s_e[TJS][EP];        // 12 KB
    __shared__ __half2 s_k[2][KH][TJS];     // 16 KB k chunk double buffer
    __shared__ __half2 s_q[H2_][QT];        // 4 KB
    __shared__ __half2 s_w[H2_];
    __shared__ float   s_psum[8][QT];
    __shared__ float   s_inv[QT];
    __shared__ int     s_last;

    const int qt = blockIdx.x >> 2;
    const int s  = blockIdx.x & 3;
    const int b  = qt >> 4;
    const int q0 = (qt & 15) * QT;
    const int tid = threadIdx.x, warp = tid >> 5, lane = tid & 31;
    const int vl = valid_lens[b];
    const bool uniform = (vl == 0);
    const int jb = s * TJS;
    int vll = uniform ? TJS : (vl - jb);
    vll = vll < 0 ? 0 : (vll > TJS ? TJS : vll);

    if (vll > 0) {
        const int jl = warp * 32 + lane;                 // 0..255
        float e[QT];

        if (uniform) {
#pragma unroll
            for (int q = 0; q < QT; q++) e[q] = 1.f;
            __syncthreads();        // keep CTA convergent before s_e writes
        } else {
            if (tid < H2_) s_w[tid] = __floats2half2_rn(wv[2 * tid], wv[2 * tid + 1]);
            for (int i = tid; i < H2_ * QT; i += NTH) {
                int h2 = i >> 3, q = i & 7;
                s_q[h2][q] = ((const __half2*)g_qh)[(size_t)(b * LQ_ + q0 + q) * H2_ + h2];
            }

            const __half2* kbase = g_kT + (size_t)b * H2_ * LK_ + jb;
            auto load_chunk = [&](int c) {
                // chunk = KH rows x 256 half2 = 8 KB; thread covers 8 half2 = 32B = 2x cp16
                const int row = tid >> 5, seg = (tid & 31) * 8;
                const __half2* src = kbase + (size_t)(c * KH + row) * LK_ + seg;
                cp16(&s_k[c & 1][row][seg],     src);
                cp16(&s_k[c & 1][row][seg + 4], src + 4);
                asm volatile("cp.async.commit_group;" ::: "memory");
            };

            const bool wmask = (warp * 32 < vll);        // warp computes?
            float acc[QT];
#pragma unroll
            for (int q = 0; q < QT; q++) acc[q] = 0.f;

            load_chunk(0);
            load_chunk(1);
            __syncthreads();   // also covers s_q/s_w staging

            for (int c = 0; c < NCH; c++) {
                if (c < NCH - 1) {
                    asm volatile("cp.async.wait_group 1;" ::: "memory");
                } else {
                    asm volatile("cp.async.wait_group 0;" ::: "memory");  // drain last chunk
                }
                __syncthreads();
                if (wmask) {
                    const int buf = c & 1;
#pragma unroll
                    for (int gg = 0; gg < 2; gg++) {
                        __half2 ah[QT];
#pragma unroll
                        for (int q = 0; q < QT; q++) ah[q] = __floats2half2_rn(0.f, 0.f);
#pragma unroll
                        for (int hh = 0; hh < 4; hh++) {
                            const int hl = gg * 4 + hh;
                            const int h2 = c * KH + hl;
                            const __half2 k2 = s_k[buf][hl][jl];
                            const __half2 w2 = s_w[h2];
                            const uint4 qa = *(const uint4*)&s_q[h2][0];
                            const uint4 qb = *(const uint4*)&s_q[h2][4];
                            const __half2* qv = (const __half2*)&qa;
                            const __half2* qw = (const __half2*)&qb;
#pragma unroll
                            for (int q = 0; q < 4; q++)
                                ah[q] = __hfma2(htanh2(__hadd2(qv[q], k2)), w2, ah[q]);
#pragma unroll
                            for (int q = 0; q < 4; q++)
                                ah[4 + q] = __hfma2(htanh2(__hadd2(qw[q], k2)), w2, ah[4 + q]);
                        }
#pragma unroll
                        for (int q = 0; q < QT; q++) {
                            float2 f = __half22float2(ah[q]);
                            acc[q] += f.x + f.y;
                        }
                    }
                }
                __syncthreads();
                if (c + 2 < NCH) load_chunk(c + 2);
            }

#pragma unroll
            for (int q = 0; q < QT; q++)
                e[q] = (wmask && jl < vll) ? __expf(acc[q]) : 0.f;
        }

        *(float4*)&s_e[jl][0] = make_float4(e[0], e[1], e[2], e[3]);
        *(float4*)&s_e[jl][4] = make_float4(e[4], e[5], e[6], e[7]);
#pragma unroll
        for (int q = 0; q < QT; q++) {
            float sq = warp_sum(e[q]);
            if (lane == 0) s_psum[warp][q] = sq;
        }
        __syncthreads();

        if (warp == 0 && lane < QT) {
            float t = 0.f;
#pragma unroll
            for (int w = 0; w < 8; w++) t += s_psum[w][lane];
            g_psum[qt][s][lane] = t;
        }

        // ---- Phase 3: partial AV, q-pair packed f32x2 FMA ----
        {
            const int c = warp * 64 + lane * 2;
            const float* vb = values + (size_t)b * LK_ * DV_ + (size_t)jb * DV_ + c;
            unsigned long long acc2[4][2];
#pragma unroll
            for (int p = 0; p < 4; p++) { acc2[p][0] = 0ull; acc2[p][1] = 0ull; }

            const int jlim = uniform ? TJS : vll;
#pragma unroll 8
            for (int j = 0; j < jlim; j++) {
                const ulonglong2 ea = *(const ulonglong2*)&s_e[j][0];
                const ulonglong2 eb = *(const ulonglong2*)&s_e[j][4];
                const float2 v = *(const float2*)(vb + (size_t)j * DV_);
                unsigned long long vx, vy;
                asm("mov.b64 %0, {%1, %1};" : "=l"(vx) : "f"(v.x));
                asm("mov.b64 %0, {%1, %1};" : "=l"(vy) : "f"(v.y));
                asm("fma.rn.f32x2 %0, %1, %2, %0;" : "+l"(acc2[0][0]) : "l"(ea.x), "l"(vx));
                asm("fma.rn.f32x2 %0, %1, %2, %0;" : "+l"(acc2[0][1]) : "l"(ea.x), "l"(vy));
                asm("fma.rn.f32x2 %0, %1, %2, %0;" : "+l"(acc2[1][0]) : "l"(ea.y), "l"(vx));
                asm("fma.rn.f32x2 %0, %1, %2, %0;" : "+l"(acc2[1][1]) : "l"(ea.y), "l"(vy));
                asm("fma.rn.f32x2 %0, %1, %2, %0;" : "+l"(acc2[2][0]) : "l"(eb.x), "l"(vx));
                asm("fma.rn.f32x2 %0, %1, %2, %0;" : "+l"(acc2[2][1]) : "l"(eb.x), "l"(vy));
                asm("fma.rn.f32x2 %0, %1, %2, %0;" : "+l"(acc2[3][0]) : "l"(eb.y), "l"(vx));
                asm("fma.rn.f32x2 %0, %1, %2, %0;" : "+l"(acc2[3][1]) : "l"(eb.y), "l"(vy));
            }
#pragma unroll
            for (int p = 0; p < 4; p++) {
                float l0, h0, l1, h1;
                asm("mov.b64 {%0, %1}, %2;" : "=f"(l0), "=f"(h0) : "l"(acc2[p][0]));
                asm("mov.b64 {%0, %1}, %2;" : "=f"(l1), "=f"(h1) : "l"(acc2[p][1]));
                *(float2*)&g_pAV[qt][s][2 * p][c]     = make_float2(l0, l1);
                *(float2*)&g_pAV[qt][s][2 * p + 1][c] = make_float2(h0, h1);
            }
        }
    }

    // ---- Ticket: last split CTA for this qtile performs the reduction ----
    __syncthreads();
    if (tid == 0) {
        __threadfence();
        unsigned o = atomicAdd(&g_tick[qt], 1u);
        s_last = (o == SPL - 1u) ? 1 : 0;
    }
    __syncthreads();
    if (!s_last) return;
    __threadfence();

    const int nact = uniform ? SPL : ((vl + TJS - 1) / TJS);
    if (tid < QT) {
        float t = 0.f;
        for (int ss = 0; ss < nact; ss++) t += g_psum[qt][ss][tid];
        s_inv[tid] = 1.f / t;
    }
    __syncthreads();

    for (int i = tid; i < QT * (DV_ / 4); i += NTH) {
        const int q = i >> 7, c = (i & 127) * 4;
        float4 a = make_float4(0.f, 0.f, 0.f, 0.f);
        for (int ss = 0; ss < nact; ss++) {
            float4 p = *(const float4*)&g_pAV[qt][ss][q][c];
            a.x += p.x; a.y += p.y; a.z += p.z; a.w += p.w;
        }
        const float inv = s_inv[q];
        *(float4*)&out[(size_t)(b * LQ_ + q0 + q) * DV_ + c] =
            make_float4(a.x * inv, a.y * inv, a.z * inv, a.w * inv);
    }
}

extern "C" void kernel_launch(void* const* d_in, const int* in_sizes, int n_in,
                              void* d_out, int out_size) {
    const float* queries = (const float*)d_in[0];
    const float* keys    = (const float*)d_in[1];
    const float* values  = (const float*)d_in[2];
    const float* Wq      = (const float*)d_in[3];
    const float* Wk      = (const float*)d_in[4];
    const float* wv      = (const float*)d_in[5];
    const int*   vlen    = (const int*)d_in[6];
    float* out = (float*)d_out;

    to_half<<<1024, 256>>>(queries, keys, Wq, Wk);
    proj_mma<<<dim3(H_ / 64, 16 + 128), 128>>>();
    partial_attn<<<NQT * SPL, NTH>>>(values, wv, vlen, out);
}

// round 16
// speedup vs baseline: 1.0043x; 1.0043x over previous
#include <cuda_runtime.h>
#include <cuda_fp16.h>

// AdditiveAttention: out[b,i,:] = softmax_j( sum_h tanh(qp+kp)*wv, mask j<vl ) @ values
// B=8, LQ=128, LK=1024, D=512, H=256, DV=512

static constexpr int B_  = 8;
static constexpr int LQ_ = 128;
static constexpr int LK_ = 1024;
static constexpr int D_  = 512;
static constexpr int H_  = 256;
static constexpr int H2_ = 128;
static constexpr int DV_ = 512;
static constexpr int QT  = 8;
static constexpr int SPL = 4;      // key splits
static constexpr int TJS = 256;    // keys per split
static constexpr int NTH = 256;    // 8 warps
static constexpr int EP  = 12;     // padded s_e row
static constexpr int KH  = 8;      // h2 rows per k-chunk
static constexpr int NCH = H2_ / KH;  // 16 chunks
static constexpr int NQT = B_ * (LQ_ / QT);   // 128 q-tiles
static constexpr int AROWS = B_ * LQ_ + B_ * LK_;

__device__ __half  g_Ah[AROWS * D_];         // fp16 copy of [queries; keys]
__device__ __half  g_Whq[D_ * H_];           // fp16 Wq
__device__ __half  g_Whk[D_ * H_];           // fp16 Wk
__device__ __half  g_qh[B_ * LQ_ * H_];      // q proj [row][h] fp16
__device__ __half2 g_kT[B_ * H2_ * LK_];     // k proj transposed [b][h2][j]
__device__ float   g_pAV[NQT][SPL][QT][DV_]; // partial e*V
__device__ float   g_psum[NQT][SPL][QT];     // partial sum(e)
__device__ unsigned g_tick[NQT];             // split completion tickets

// ---------------- helpers ----------------
__device__ __forceinline__ void cp16(void* dst, const void* src) {
    unsigned d = (unsigned)__cvta_generic_to_shared(dst);
    asm volatile("cp.async.cg.shared.global [%0], [%1], 16;" :: "r"(d), "l"(src));
}
__device__ __forceinline__ void ldsm_x4(unsigned* r, const void* p) {
    unsigned addr = (unsigned)__cvta_generic_to_shared(p);
    asm volatile("ldmatrix.sync.aligned.m8n8.x4.shared.b16 {%0,%1,%2,%3}, [%4];"
                 : "=r"(r[0]), "=r"(r[1]), "=r"(r[2]), "=r"(r[3]) : "r"(addr));
}
__device__ __forceinline__ void ldsm_x4_t(unsigned* r, const void* p) {
    unsigned addr = (unsigned)__cvta_generic_to_shared(p);
    asm volatile("ldmatrix.sync.aligned.m8n8.x4.trans.shared.b16 {%0,%1,%2,%3}, [%4];"
                 : "=r"(r[0]), "=r"(r[1]), "=r"(r[2]), "=r"(r[3]) : "r"(addr));
}
__device__ __forceinline__ void mma_f16(float* c, const unsigned* a, const unsigned* b) {
    asm volatile(
        "mma.sync.aligned.m16n8k16.row.col.f32.f16.f16.f32 "
        "{%0,%1,%2,%3}, {%4,%5,%6,%7}, {%8,%9}, {%0,%1,%2,%3};"
        : "+f"(c[0]), "+f"(c[1]), "+f"(c[2]), "+f"(c[3])
        : "r"(a[0]), "r"(a[1]), "r"(a[2]), "r"(a[3]), "r"(b[0]), "r"(b[1]));
}
__device__ __forceinline__ __half2 htanh2(__half2 x) {
    unsigned xi = *reinterpret_cast<unsigned*>(&x), yi;
    asm("tanh.approx.f16x2 %0, %1;" : "=r"(yi) : "r"(xi));
    return *reinterpret_cast<__half2*>(&yi);
}
__device__ __forceinline__ float warp_sum(float v) {
#pragma unroll
    for (int off = 16; off; off >>= 1) v += __shfl_xor_sync(0xffffffffu, v, off);
    return v;
}

// ---------------- convert inputs to fp16 ----------------
static constexpr int NQ4 = B_ * LQ_ * D_ / 4;
static constexpr int NK4 = B_ * LK_ * D_ / 4;
static constexpr int NW4 = D_ * H_ / 4;
static constexpr int TOT4 = NQ4 + NK4 + 2 * NW4;

__global__ __launch_bounds__(256) void to_half(const float* __restrict__ q,
                                               const float* __restrict__ k,
                                               const float* __restrict__ wq,
                                               const float* __restrict__ wk) {
    for (int i = blockIdx.x * 256 + threadIdx.x; i < TOT4; i += gridDim.x * 256) {
        const float4* src; __half* dst; int off;
        if (i < NQ4)                   { src = (const float4*)q;  dst = g_Ah;                off = i; }
        else if (i < NQ4 + NK4)        { src = (const float4*)k;  dst = g_Ah + (size_t)B_ * LQ_ * D_; off = i - NQ4; }
        else if (i < NQ4 + NK4 + NW4)  { src = (const float4*)wq; dst = g_Whq;              off = i - NQ4 - NK4; }
        else                           { src = (const float4*)wk; dst = g_Whk;              off = i - NQ4 - NK4 - NW4; }
        float4 v = src[off];
        *(__half2*)&dst[(size_t)off * 4]     = __floats2half2_rn(v.x, v.y);
        *(__half2*)&dst[(size_t)off * 4 + 2] = __floats2half2_rn(v.z, v.w);
    }
}

// ---------------- ticket reset (3rd launch -> partial_attn lands at launch #4) ----------------
__global__ __launch_bounds__(128) void reset_tick() {
    if (threadIdx.x < NQT) g_tick[threadIdx.x] = 0u;
}

// ---------------- projections: fp16 mma + ldmatrix + 2-stage cp.async ----------------
__global__ __launch_bounds__(128) void proj_mma() {
    __shared__ __half As[2][64][40];
    __shared__ __half Ws[2][32][72];

    const bool is_q = (blockIdx.y < 16);
    const int m0 = (is_q ? blockIdx.y : (blockIdx.y - 16)) * 64;
    const int n0 = blockIdx.x * 64;
    const __half* Asrc = g_Ah + (size_t)((is_q ? 0 : B_ * LQ_) + m0) * D_;
    const __half* Wsrc = is_q ? g_Whq : g_Whk;

    const int tid = threadIdx.x, warp = tid >> 5, lane = tid & 31;
    const int wm = (warp & 1) * 32, wn = (warp >> 1) * 32;
    const int g = lane >> 2, tg = lane & 3;

    float c[2][4][4];
#pragma unroll
    for (int mt = 0; mt < 2; mt++)
#pragma unroll
        for (int nt = 0; nt < 4; nt++)
#pragma unroll
            for (int i = 0; i < 4; i++) c[mt][nt][i] = 0.f;

    auto load_stage = [&](int buf, int k0) {
#pragma unroll
        for (int cc = tid; cc < 256; cc += 128) {
            int row = cc >> 2, col8 = (cc & 3) * 8;
            cp16(&As[buf][row][col8], Asrc + (size_t)row * D_ + k0 + col8);
        }
#pragma unroll
        for (int cc = tid; cc < 256; cc += 128) {
            int row = cc >> 3, col8 = (cc & 7) * 8;
            cp16(&Ws[buf][row][col8], Wsrc + (size_t)(k0 + row) * H_ + n0 + col8);
        }
        asm volatile("cp.async.commit_group;" ::: "memory");
    };

    load_stage(0, 0);
    for (int t = 0; t < 16; t++) {
        if (t + 1 < 16) {
            load_stage((t + 1) & 1, (t + 1) * 32);
            asm volatile("cp.async.wait_group 1;" ::: "memory");
        } else {
            asm volatile("cp.async.wait_group 0;" ::: "memory");
        }
        __syncthreads();
        const int buf = t & 1;
#pragma unroll
        for (int ks = 0; ks < 2; ks++) {
            unsigned a[2][4], bf[2][4];
#pragma unroll
            for (int mt = 0; mt < 2; mt++)
                ldsm_x4(a[mt], &As[buf][wm + mt * 16 + (lane & 15)][ks * 16 + ((lane >> 4) << 3)]);
#pragma unroll
            for (int np = 0; np < 2; np++)
                ldsm_x4_t(bf[np], &Ws[buf][ks * 16 + (lane & 15)][wn + np * 16 + ((lane >> 4) << 3)]);
#pragma unroll
            for (int mt = 0; mt < 2; mt++)
#pragma unroll
                for (int np = 0; np < 2; np++) {
                    mma_f16(c[mt][np * 2],     a[mt], &bf[np][0]);
                    mma_f16(c[mt][np * 2 + 1], a[mt], &bf[np][2]);
                }
        }
        __syncthreads();
    }

#pragma unroll
    for (int mt = 0; mt < 2; mt++)
#pragma unroll
        for (int nt = 0; nt < 4; nt++) {
            int row = m0 + wm + mt * 16 + g;
            int col = n0 + wn + nt * 8 + tg * 2;
            __half2 lo = __floats2half2_rn(c[mt][nt][0], c[mt][nt][1]);
            __half2 hi = __floats2half2_rn(c[mt][nt][2], c[mt][nt][3]);
            if (is_q) {
                *(__half2*)&g_qh[(size_t)row * H_ + col] = lo;
                *(__half2*)&g_qh[(size_t)(row + 8) * H_ + col] = hi;
            } else {
                int b_ = row >> 10, j = row & 1023;
                int h2 = col >> 1;
                g_kT[((size_t)b_ * H2_ + h2) * LK_ + j] = lo;
                g_kT[((size_t)b_ * H2_ + h2) * LK_ + (j + 8)] = hi;
            }
        }
}

// ---------------- split-K partial attention + fused last-CTA reduce ----------------
__global__ __launch_bounds__(NTH, 2) void partial_attn(
    const float* __restrict__ values,
    const float* __restrict__ wv,
    const int* __restrict__ valid_lens,
    float* __restrict__ out) {
    __shared__ float   s_e[TJS][EP];        // 12 KB
    __shared__ __half2 s_k[2][KH][TJS];     // 16 KB k chunk double buffer
    __shared__ __half2 s_q[H2_][QT];        // 4 KB
    __shared__ __half2 s_w[H2_];
    __shared__ float   s_psum[8][QT];
    __shared__ float   s_inv[QT];
    __shared__ int     s_last;

    const int qt = blockIdx.x >> 2;
    const int s  = blockIdx.x & 3;
    const int b  = qt >> 4;
    const int q0 = (qt & 15) * QT;
    const int tid = threadIdx.x, warp = tid >> 5, lane = tid & 31;
    const int vl = valid_lens[b];
    const bool uniform = (vl == 0);
    const int jb = s * TJS;
    int vll = uniform ? TJS : (vl - jb);
    vll = vll < 0 ? 0 : (vll > TJS ? TJS : vll);

    if (vll > 0) {
        const int jl = warp * 32 + lane;                 // 0..255
        float e[QT];

        if (uniform) {
#pragma unroll
            for (int q = 0; q < QT; q++) e[q] = 1.f;
            __syncthreads();        // keep CTA convergent before s_e writes
        } else {
            if (tid < H2_) s_w[tid] = __floats2half2_rn(wv[2 * tid], wv[2 * tid + 1]);
            for (int i = tid; i < H2_ * QT; i += NTH) {
                int h2 = i >> 3, q = i & 7;
                s_q[h2][q] = ((const __half2*)g_qh)[(size_t)(b * LQ_ + q0 + q) * H2_ + h2];
            }

            const __half2* kbase = g_kT + (size_t)b * H2_ * LK_ + jb;
            auto load_chunk = [&](int c) {
                // chunk = KH rows x 256 half2 = 8 KB; thread covers 8 half2 = 32B = 2x cp16
                const int row = tid >> 5, seg = (tid & 31) * 8;
                const __half2* src = kbase + (size_t)(c * KH + row) * LK_ + seg;
                cp16(&s_k[c & 1][row][seg],     src);
                cp16(&s_k[c & 1][row][seg + 4], src + 4);
                asm volatile("cp.async.commit_group;" ::: "memory");
            };

            const bool wmask = (warp * 32 < vll);        // warp computes?
            float acc[QT];
#pragma unroll
            for (int q = 0; q < QT; q++) acc[q] = 0.f;

            load_chunk(0);
            load_chunk(1);
            __syncthreads();   // also covers s_q/s_w staging

            for (int c = 0; c < NCH; c++) {
                if (c < NCH - 1) {
                    asm volatile("cp.async.wait_group 1;" ::: "memory");
                } else {
                    asm volatile("cp.async.wait_group 0;" ::: "memory");  // drain last chunk
                }
                __syncthreads();
                if (wmask) {
                    const int buf = c & 1;
#pragma unroll
                    for (int gg = 0; gg < 2; gg++) {
                        __half2 ah[QT];
#pragma unroll
                        for (int q = 0; q < QT; q++) ah[q] = __floats2half2_rn(0.f, 0.f);
#pragma unroll
                        for (int hh = 0; hh < 4; hh++) {
                            const int hl = gg * 4 + hh;
                            const int h2 = c * KH + hl;
                            const __half2 k2 = s_k[buf][hl][jl];
                            const __half2 w2 = s_w[h2];
                            const uint4 qa = *(const uint4*)&s_q[h2][0];
                            const uint4 qb = *(const uint4*)&s_q[h2][4];
                            const __half2* qv = (const __half2*)&qa;
                            const __half2* qw = (const __half2*)&qb;
#pragma unroll
                            for (int q = 0; q < 4; q++)
                                ah[q] = __hfma2(htanh2(__hadd2(qv[q], k2)), w2, ah[q]);
#pragma unroll
                            for (int q = 0; q < 4; q++)
                                ah[4 + q] = __hfma2(htanh2(__hadd2(qw[q], k2)), w2, ah[4 + q]);
                        }
#pragma unroll
                        for (int q = 0; q < QT; q++) {
                            float2 f = __half22float2(ah[q]);
                            acc[q] += f.x + f.y;
                        }
                    }
                }
                __syncthreads();
                if (c + 2 < NCH) load_chunk(c + 2);
            }

#pragma unroll
            for (int q = 0; q < QT; q++)
                e[q] = (wmask && jl < vll) ? __expf(acc[q]) : 0.f;
        }

        *(float4*)&s_e[jl][0] = make_float4(e[0], e[1], e[2], e[3]);
        *(float4*)&s_e[jl][4] = make_float4(e[4], e[5], e[6], e[7]);
#pragma unroll
        for (int q = 0; q < QT; q++) {
            float sq = warp_sum(e[q]);
            if (lane == 0) s_psum[warp][q] = sq;
        }
        __syncthreads();

        if (warp == 0 && lane < QT) {
            float t = 0.f;
#pragma unroll
            for (int w = 0; w < 8; w++) t += s_psum[w][lane];
            g_psum[qt][s][lane] = t;
        }

        // ---- Phase 3: partial AV, q-pair packed f32x2 FMA ----
        {
            const int c = warp * 64 + lane * 2;
            const float* vb = values + (size_t)b * LK_ * DV_ + (size_t)jb * DV_ + c;
            unsigned long long acc2[4][2];
#pragma unroll
            for (int p = 0; p < 4; p++) { acc2[p][0] = 0ull; acc2[p][1] = 0ull; }

            const int jlim = uniform ? TJS : vll;
#pragma unroll 8
            for (int j = 0; j < jlim; j++) {
                const ulonglong2 ea = *(const ulonglong2*)&s_e[j][0];
                const ulonglong2 eb = *(const ulonglong2*)&s_e[j][4];
                const float2 v = *(const float2*)(vb + (size_t)j * DV_);
                unsigned long long vx, vy;
                asm("mov.b64 %0, {%1, %1};" : "=l"(vx) : "f"(v.x));
                asm("mov.b64 %0, {%1, %1};" : "=l"(vy) : "f"(v.y));
                asm("fma.rn.f32x2 %0, %1, %2, %0;" : "+l"(acc2[0][0]) : "l"(ea.x), "l"(vx));
                asm("fma.rn.f32x2 %0, %1, %2, %0;" : "+l"(acc2[0][1]) : "l"(ea.x), "l"(vy));
                asm("fma.rn.f32x2 %0, %1, %2, %0;" : "+l"(acc2[1][0]) : "l"(ea.y), "l"(vx));
                asm("fma.rn.f32x2 %0, %1, %2, %0;" : "+l"(acc2[1][1]) : "l"(ea.y), "l"(vy));
                asm("fma.rn.f32x2 %0, %1, %2, %0;" : "+l"(acc2[2][0]) : "l"(eb.x), "l"(vx));
                asm("fma.rn.f32x2 %0, %1, %2, %0;" : "+l"(acc2[2][1]) : "l"(eb.x), "l"(vy));
                asm("fma.rn.f32x2 %0, %1, %2, %0;" : "+l"(acc2[3][0]) : "l"(eb.y), "l"(vx));
                asm("fma.rn.f32x2 %0, %1, %2, %0;" : "+l"(acc2[3][1]) : "l"(eb.y), "l"(vy));
            }
#pragma unroll
            for (int p = 0; p < 4; p++) {
                float l0, h0, l1, h1;
                asm("mov.b64 {%0, %1}, %2;" : "=f"(l0), "=f"(h0) : "l"(acc2[p][0]));
                asm("mov.b64 {%0, %1}, %2;" : "=f"(l1), "=f"(h1) : "l"(acc2[p][1]));
                *(float2*)&g_pAV[qt][s][2 * p][c]     = make_float2(l0, l1);
                *(float2*)&g_pAV[qt][s][2 * p + 1][c] = make_float2(h0, h1);
            }
        }
    }

    // ---- Ticket: last split CTA for this qtile performs the reduction ----
    __syncthreads();
    if (tid == 0) {
        __threadfence();
        unsigned o = atomicAdd(&g_tick[qt], 1u);
        s_last = (o == SPL - 1u) ? 1 : 0;
    }
    __syncthreads();
    if (!s_last) return;
    __threadfence();

    const int nact = uniform ? SPL : ((vl + TJS - 1) / TJS);
    if (tid < QT) {
        float t = 0.f;
        for (int ss = 0; ss < nact; ss++) t += g_psum[qt][ss][tid];
        s_inv[tid] = 1.f / t;
    }
    __syncthreads();

    for (int i = tid; i < QT * (DV_ / 4); i += NTH) {
        const int q = i >> 7, c = (i & 127) * 4;
        float4 a = make_float4(0.f, 0.f, 0.f, 0.f);
        for (int ss = 0; ss < nact; ss++) {
            float4 p = *(const float4*)&g_pAV[qt][ss][q][c];
            a.x += p.x; a.y += p.y; a.z += p.z; a.w += p.w;
        }
        const float inv = s_inv[q];
        *(float4*)&out[(size_t)(b * LQ_ + q0 + q) * DV_ + c] =
            make_float4(a.x * inv, a.y * inv, a.z * inv, a.w * inv);
    }
}

extern "C" void kernel_launch(void* const* d_in, const int* in_sizes, int n_in,
                              void* d_out, int out_size) {
    const float* queries = (const float*)d_in[0];
    const float* keys    = (const float*)d_in[1];
    const float* values  = (const float*)d_in[2];
    const float* Wq      = (const float*)d_in[3];
    const float* Wk      = (const float*)d_in[4];
    const float* wv      = (const float*)d_in[5];
    const int*   vlen    = (const int*)d_in[6];
    float* out = (float*)d_out;

    to_half<<<1024, 256>>>(queries, keys, Wq, Wk);
    proj_mma<<<dim3(H_ / 64, 16 + 128), 128>>>();
    reset_tick<<<1, 128>>>();                 // 3rd launch: puts partial_attn at launch #4
    partial_attn<<<NQT * SPL, NTH>>>(values, wv, vlen, out);
}

// round 17
// speedup vs baseline: 1.0538x; 1.0493x over previous
#include <cuda_runtime.h>
#include <cuda_fp16.h>

// AdditiveAttention: out[b,i,:] = softmax_j( sum_h tanh(qp+kp)*wv, mask j<vl ) @ values
// B=8, LQ=128, LK=1024, D=512, H=256, DV=512

static constexpr int B_  = 8;
static constexpr int LQ_ = 128;
static constexpr int LK_ = 1024;
static constexpr int D_  = 512;
static constexpr int H_  = 256;
static constexpr int H2_ = 128;
static constexpr int DV_ = 512;
static constexpr int QT  = 8;
static constexpr int SPL = 8;      // key splits
static constexpr int TJS = 128;    // keys per split
static constexpr int NTH = 128;    // 4 warps
static constexpr int EP  = 12;     // padded s_e row
static constexpr int KH  = 8;      // h2 rows per k-chunk
static constexpr int NCH = H2_ / KH;  // 16 chunks
static constexpr int NQT = B_ * (LQ_ / QT);   // 128 q-tiles
static constexpr int AROWS = B_ * LQ_ + B_ * LK_;

__device__ __half  g_Ah[AROWS * D_];         // fp16 copy of [queries; keys]
__device__ __half  g_Whq[D_ * H_];           // fp16 Wq
__device__ __half  g_Whk[D_ * H_];           // fp16 Wk
__device__ __half  g_qh[B_ * LQ_ * H_];      // q proj [row][h] fp16
__device__ __half2 g_kT[B_ * H2_ * LK_];     // k proj transposed [b][h2][j]
__device__ float   g_pAV[NQT][SPL][QT][DV_]; // partial e*V (16 MB)
__device__ float   g_psum[NQT][SPL][QT];     // partial sum(e)
__device__ unsigned g_tick[NQT];             // split completion tickets

// ---------------- helpers ----------------
__device__ __forceinline__ void cp16(void* dst, const void* src) {
    unsigned d = (unsigned)__cvta_generic_to_shared(dst);
    asm volatile("cp.async.cg.shared.global [%0], [%1], 16;" :: "r"(d), "l"(src));
}
__device__ __forceinline__ void ldsm_x4(unsigned* r, const void* p) {
    unsigned addr = (unsigned)__cvta_generic_to_shared(p);
    asm volatile("ldmatrix.sync.aligned.m8n8.x4.shared.b16 {%0,%1,%2,%3}, [%4];"
                 : "=r"(r[0]), "=r"(r[1]), "=r"(r[2]), "=r"(r[3]) : "r"(addr));
}
__device__ __forceinline__ void ldsm_x4_t(unsigned* r, const void* p) {
    unsigned addr = (unsigned)__cvta_generic_to_shared(p);
    asm volatile("ldmatrix.sync.aligned.m8n8.x4.trans.shared.b16 {%0,%1,%2,%3}, [%4];"
                 : "=r"(r[0]), "=r"(r[1]), "=r"(r[2]), "=r"(r[3]) : "r"(addr));
}
__device__ __forceinline__ void mma_f16(float* c, const unsigned* a, const unsigned* b) {
    asm volatile(
        "mma.sync.aligned.m16n8k16.row.col.f32.f16.f16.f32 "
        "{%0,%1,%2,%3}, {%4,%5,%6,%7}, {%8,%9}, {%0,%1,%2,%3};"
        : "+f"(c[0]), "+f"(c[1]), "+f"(c[2]), "+f"(c[3])
        : "r"(a[0]), "r"(a[1]), "r"(a[2]), "r"(a[3]), "r"(b[0]), "r"(b[1]));
}
__device__ __forceinline__ __half2 htanh2(__half2 x) {
    unsigned xi = *reinterpret_cast<unsigned*>(&x), yi;
    asm("tanh.approx.f16x2 %0, %1;" : "=r"(yi) : "r"(xi));
    return *reinterpret_cast<__half2*>(&yi);
}
__device__ __forceinline__ float warp_sum(float v) {
#pragma unroll
    for (int off = 16; off; off >>= 1) v += __shfl_xor_sync(0xffffffffu, v, off);
    return v;
}

// ---------------- convert inputs to fp16 ----------------
static constexpr int NQ4 = B_ * LQ_ * D_ / 4;
static constexpr int NK4 = B_ * LK_ * D_ / 4;
static constexpr int NW4 = D_ * H_ / 4;
static constexpr int TOT4 = NQ4 + NK4 + 2 * NW4;

__global__ __launch_bounds__(256) void to_half(const float* __restrict__ q,
                                               const float* __restrict__ k,
                                               const float* __restrict__ wq,
                                               const float* __restrict__ wk) {
    for (int i = blockIdx.x * 256 + threadIdx.x; i < TOT4; i += gridDim.x * 256) {
        const float4* src; __half* dst; int off;
        if (i < NQ4)                   { src = (const float4*)q;  dst = g_Ah;                off = i; }
        else if (i < NQ4 + NK4)        { src = (const float4*)k;  dst = g_Ah + (size_t)B_ * LQ_ * D_; off = i - NQ4; }
        else if (i < NQ4 + NK4 + NW4)  { src = (const float4*)wq; dst = g_Whq;              off = i - NQ4 - NK4; }
        else                           { src = (const float4*)wk; dst = g_Whk;              off = i - NQ4 - NK4 - NW4; }
        float4 v = src[off];
        *(__half2*)&dst[(size_t)off * 4]     = __floats2half2_rn(v.x, v.y);
        *(__half2*)&dst[(size_t)off * 4 + 2] = __floats2half2_rn(v.z, v.w);
    }
}

// ---------------- ticket reset (3rd launch -> partial_attn lands at launch #4) ----------------
__global__ __launch_bounds__(128) void reset_tick() {
    if (threadIdx.x < NQT) g_tick[threadIdx.x] = 0u;
}

// ---------------- projections: fp16 mma + ldmatrix + 2-stage cp.async ----------------
__global__ __launch_bounds__(128) void proj_mma() {
    __shared__ __half As[2][64][40];
    __shared__ __half Ws[2][32][72];

    const bool is_q = (blockIdx.y < 16);
    const int m0 = (is_q ? blockIdx.y : (blockIdx.y - 16)) * 64;
    const int n0 = blockIdx.x * 64;
    const __half* Asrc = g_Ah + (size_t)((is_q ? 0 : B_ * LQ_) + m0) * D_;
    const __half* Wsrc = is_q ? g_Whq : g_Whk;

    const int tid = threadIdx.x, warp = tid >> 5, lane = tid & 31;
    const int wm = (warp & 1) * 32, wn = (warp >> 1) * 32;
    const int g = lane >> 2, tg = lane & 3;

    float c[2][4][4];
#pragma unroll
    for (int mt = 0; mt < 2; mt++)
#pragma unroll
        for (int nt = 0; nt < 4; nt++)
#pragma unroll
            for (int i = 0; i < 4; i++) c[mt][nt][i] = 0.f;

    auto load_stage = [&](int buf, int k0) {
#pragma unroll
        for (int cc = tid; cc < 256; cc += 128) {
            int row = cc >> 2, col8 = (cc & 3) * 8;
            cp16(&As[buf][row][col8], Asrc + (size_t)row * D_ + k0 + col8);
        }
#pragma unroll
        for (int cc = tid; cc < 256; cc += 128) {
            int row = cc >> 3, col8 = (cc & 7) * 8;
            cp16(&Ws[buf][row][col8], Wsrc + (size_t)(k0 + row) * H_ + n0 + col8);
        }
        asm volatile("cp.async.commit_group;" ::: "memory");
    };

    load_stage(0, 0);
    for (int t = 0; t < 16; t++) {
        if (t + 1 < 16) {
            load_stage((t + 1) & 1, (t + 1) * 32);
            asm volatile("cp.async.wait_group 1;" ::: "memory");
        } else {
            asm volatile("cp.async.wait_group 0;" ::: "memory");
        }
        __syncthreads();
        const int buf = t & 1;
#pragma unroll
        for (int ks = 0; ks < 2; ks++) {
            unsigned a[2][4], bf[2][4];
#pragma unroll
            for (int mt = 0; mt < 2; mt++)
                ldsm_x4(a[mt], &As[buf][wm + mt * 16 + (lane & 15)][ks * 16 + ((lane >> 4) << 3)]);
#pragma unroll
            for (int np = 0; np < 2; np++)
                ldsm_x4_t(bf[np], &Ws[buf][ks * 16 + (lane & 15)][wn + np * 16 + ((lane >> 4) << 3)]);
#pragma unroll
            for (int mt = 0; mt < 2; mt++)
#pragma unroll
                for (int np = 0; np < 2; np++) {
                    mma_f16(c[mt][np * 2],     a[mt], &bf[np][0]);
                    mma_f16(c[mt][np * 2 + 1], a[mt], &bf[np][2]);
                }
        }
        __syncthreads();
    }

#pragma unroll
    for (int mt = 0; mt < 2; mt++)
#pragma unroll
        for (int nt = 0; nt < 4; nt++) {
            int row = m0 + wm + mt * 16 + g;
            int col = n0 + wn + nt * 8 + tg * 2;
            __half2 lo = __floats2half2_rn(c[mt][nt][0], c[mt][nt][1]);
            __half2 hi = __floats2half2_rn(c[mt][nt][2], c[mt][nt][3]);
            if (is_q) {
                *(__half2*)&g_qh[(size_t)row * H_ + col] = lo;
                *(__half2*)&g_qh[(size_t)(row + 8) * H_ + col] = hi;
            } else {
                int b_ = row >> 10, j = row & 1023;
                int h2 = col >> 1;
                g_kT[((size_t)b_ * H2_ + h2) * LK_ + j] = lo;
                g_kT[((size_t)b_ * H2_ + h2) * LK_ + (j + 8)] = hi;
            }
        }
}

// ---------------- split-K partial attention + fused last-CTA reduce ----------------
// grid = SPL * NQT, s-major: s = blk / NQT, qt = blk % NQT  (waves span all batches)
__global__ __launch_bounds__(NTH, 4) void partial_attn(
    const float* __restrict__ values,
    const float* __restrict__ wv,
    const int* __restrict__ valid_lens,
    float* __restrict__ out) {
    __shared__ float   s_e[TJS][EP];        // 6 KB
    __shared__ __half2 s_k[2][KH][TJS];     // 8 KB k chunk double buffer
    __shared__ __half2 s_q[H2_][QT];        // 4 KB
    __shared__ __half2 s_w[H2_];
    __shared__ float   s_psum[4][QT];
    __shared__ float   s_inv[QT];
    __shared__ int     s_last;

    const int qt = blockIdx.x & (NQT - 1);
    const int s  = blockIdx.x >> 7;
    const int b  = qt >> 4;
    const int q0 = (qt & 15) * QT;
    const int tid = threadIdx.x, warp = tid >> 5, lane = tid & 31;
    const int vl = valid_lens[b];
    const bool uniform = (vl == 0);
    const int jb = s * TJS;
    int vll = uniform ? TJS : (vl - jb);
    vll = vll < 0 ? 0 : (vll > TJS ? TJS : vll);

    if (vll > 0) {
        const int jl = tid;                              // 0..127, lane owns 1 j
        float e[QT];

        if (uniform) {
#pragma unroll
            for (int q = 0; q < QT; q++) e[q] = 1.f;
            __syncthreads();        // keep CTA convergent before s_e writes
        } else {
            if (tid < H2_) s_w[tid] = __floats2half2_rn(wv[2 * tid], wv[2 * tid + 1]);
            for (int i = tid; i < H2_ * QT; i += NTH) {
                int h2 = i >> 3, q = i & 7;
                s_q[h2][q] = ((const __half2*)g_qh)[(size_t)(b * LQ_ + q0 + q) * H2_ + h2];
            }

            const __half2* kbase = g_kT + (size_t)b * H2_ * LK_ + jb;
            auto load_chunk = [&](int c) {
                // chunk = KH rows x 128 half2 = 4 KB; 128 thr x 32B = 2x cp16
                const int row = tid >> 4, seg = (tid & 15) * 8;
                const __half2* src = kbase + (size_t)(c * KH + row) * LK_ + seg;
                cp16(&s_k[c & 1][row][seg],     src);
                cp16(&s_k[c & 1][row][seg + 4], src + 4);
                asm volatile("cp.async.commit_group;" ::: "memory");
            };

            const bool wmask = (warp * 32 < vll);        // warp computes?
            float acc[QT];
#pragma unroll
            for (int q = 0; q < QT; q++) acc[q] = 0.f;

            load_chunk(0);
            load_chunk(1);
            __syncthreads();   // also covers s_q/s_w staging

            for (int c = 0; c < NCH; c++) {
                if (c < NCH - 1) {
                    asm volatile("cp.async.wait_group 1;" ::: "memory");
                } else {
                    asm volatile("cp.async.wait_group 0;" ::: "memory");  // drain last chunk
                }
                __syncthreads();
                if (wmask) {
                    const int buf = c & 1;
#pragma unroll
                    for (int gg = 0; gg < 2; gg++) {
                        __half2 ah[QT];
#pragma unroll
                        for (int q = 0; q < QT; q++) ah[q] = __floats2half2_rn(0.f, 0.f);
#pragma unroll
                        for (int hh = 0; hh < 4; hh++) {
                            const int hl = gg * 4 + hh;
                            const int h2 = c * KH + hl;
                            const __half2 k2 = s_k[buf][hl][jl];
                            const __half2 w2 = s_w[h2];
                            const uint4 qa = *(const uint4*)&s_q[h2][0];
                            const uint4 qb = *(const uint4*)&s_q[h2][4];
                            const __half2* qv = (const __half2*)&qa;
                            const __half2* qw = (const __half2*)&qb;
#pragma unroll
                            for (int q = 0; q < 4; q++)
                                ah[q] = __hfma2(htanh2(__hadd2(qv[q], k2)), w2, ah[q]);
#pragma unroll
                            for (int q = 0; q < 4; q++)
                                ah[4 + q] = __hfma2(htanh2(__hadd2(qw[q], k2)), w2, ah[4 + q]);
                        }
#pragma unroll
                        for (int q = 0; q < QT; q++) {
                            float2 f = __half22float2(ah[q]);
                            acc[q] += f.x + f.y;
                        }
                    }
                }
                __syncthreads();
                if (c + 2 < NCH) load_chunk(c + 2);
            }

#pragma unroll
            for (int q = 0; q < QT; q++)
                e[q] = (wmask && jl < vll) ? __expf(acc[q]) : 0.f;
        }

        *(float4*)&s_e[jl][0] = make_float4(e[0], e[1], e[2], e[3]);
        *(float4*)&s_e[jl][4] = make_float4(e[4], e[5], e[6], e[7]);
#pragma unroll
        for (int q = 0; q < QT; q++) {
            float sq = warp_sum(e[q]);
            if (lane == 0) s_psum[warp][q] = sq;
        }
        __syncthreads();

        if (warp == 0 && lane < QT) {
            float t = 0.f;
#pragma unroll
            for (int w = 0; w < 4; w++) t += s_psum[w][lane];
            g_psum[qt][s][lane] = t;
        }

        // ---- Phase 3: partial AV, q-pair packed f32x2 FMA; warp owns 128 cols ----
        {
            const int c0 = warp * 128 + lane * 2;        // first float2
            const int c1 = c0 + 64;                      // second float2
            const float* vb = values + (size_t)b * LK_ * DV_ + (size_t)jb * DV_;
            unsigned long long acc2[4][4];               // [qpair][col-slot]
#pragma unroll
            for (int p = 0; p < 4; p++)
#pragma unroll
                for (int x = 0; x < 4; x++) acc2[p][x] = 0ull;

            const int jlim = uniform ? TJS : vll;
#pragma unroll 4
            for (int j = 0; j < jlim; j++) {
                const ulonglong2 ea = *(const ulonglong2*)&s_e[j][0];
                const ulonglong2 eb = *(const ulonglong2*)&s_e[j][4];
                const float2 va = *(const float2*)(vb + (size_t)j * DV_ + c0);
                const float2 vc = *(const float2*)(vb + (size_t)j * DV_ + c1);
                unsigned long long v0, v1, v2, v3;
                asm("mov.b64 %0, {%1, %1};" : "=l"(v0) : "f"(va.x));
                asm("mov.b64 %0, {%1, %1};" : "=l"(v1) : "f"(va.y));
                asm("mov.b64 %0, {%1, %1};" : "=l"(v2) : "f"(vc.x));
                asm("mov.b64 %0, {%1, %1};" : "=l"(v3) : "f"(vc.y));
                asm("fma.rn.f32x2 %0, %1, %2, %0;" : "+l"(acc2[0][0]) : "l"(ea.x), "l"(v0));
                asm("fma.rn.f32x2 %0, %1, %2, %0;" : "+l"(acc2[0][1]) : "l"(ea.x), "l"(v1));
                asm("fma.rn.f32x2 %0, %1, %2, %0;" : "+l"(acc2[0][2]) : "l"(ea.x), "l"(v2));
                asm("fma.rn.f32x2 %0, %1, %2, %0;" : "+l"(acc2[0][3]) : "l"(ea.x), "l"(v3));
                asm("fma.rn.f32x2 %0, %1, %2, %0;" : "+l"(acc2[1][0]) : "l"(ea.y), "l"(v0));
                asm("fma.rn.f32x2 %0, %1, %2, %0;" : "+l"(acc2[1][1]) : "l"(ea.y), "l"(v1));
                asm("fma.rn.f32x2 %0, %1, %2, %0;" : "+l"(acc2[1][2]) : "l"(ea.y), "l"(v2));
                asm("fma.rn.f32x2 %0, %1, %2, %0;" : "+l"(acc2[1][3]) : "l"(ea.y), "l"(v3));
                asm("fma.rn.f32x2 %0, %1, %2, %0;" : "+l"(acc2[2][0]) : "l"(eb.x), "l"(v0));
                asm("fma.rn.f32x2 %0, %1, %2, %0;" : "+l"(acc2[2][1]) : "l"(eb.x), "l"(v1));
                asm("fma.rn.f32x2 %0, %1, %2, %0;" : "+l"(acc2[2][2]) : "l"(eb.x), "l"(v2));
                asm("fma.rn.f32x2 %0, %1, %2, %0;" : "+l"(acc2[2][3]) : "l"(eb.x), "l"(v3));
                asm("fma.rn.f32x2 %0, %1, %2, %0;" : "+l"(acc2[3][0]) : "l"(eb.y), "l"(v0));
                asm("fma.rn.f32x2 %0, %1, %2, %0;" : "+l"(acc2[3][1]) : "l"(eb.y), "l"(v1));
                asm("fma.rn.f32x2 %0, %1, %2, %0;" : "+l"(acc2[3][2]) : "l"(eb.y), "l"(v2));
                asm("fma.rn.f32x2 %0, %1, %2, %0;" : "+l"(acc2[3][3]) : "l"(eb.y), "l"(v3));
            }
#pragma unroll
            for (int p = 0; p < 4; p++) {
                float a0, a1, b0, b1, cx0, cx1, d0, d1;
                asm("mov.b64 {%0, %1}, %2;" : "=f"(a0), "=f"(a1) : "l"(acc2[p][0]));
                asm("mov.b64 {%0, %1}, %2;" : "=f"(b0), "=f"(b1) : "l"(acc2[p][1]));
                asm("mov.b64 {%0, %1}, %2;" : "=f"(cx0), "=f"(cx1) : "l"(acc2[p][2]));
                asm("mov.b64 {%0, %1}, %2;" : "=f"(d0), "=f"(d1) : "l"(acc2[p][3]));
                // acc2[p][0]=(q2p,q2p+1)@col c0 ; [1]@c0+1 ; [2]@c1 ; [3]@c1+1
                *(float2*)&g_pAV[qt][s][2 * p][c0]     = make_float2(a0, b0);
                *(float2*)&g_pAV[qt][s][2 * p + 1][c0] = make_float2(a1, b1);
                *(float2*)&g_pAV[qt][s][2 * p][c1]     = make_float2(cx0, d0);
                *(float2*)&g_pAV[qt][s][2 * p + 1][c1] = make_float2(cx1, d1);
            }
        }
    }

    // ---- Ticket: last split CTA for this qtile performs the reduction ----
    __syncthreads();
    if (tid == 0) {
        __threadfence();
        unsigned o = atomicAdd(&g_tick[qt], 1u);
        s_last = (o == SPL - 1u) ? 1 : 0;
    }
    __syncthreads();
    if (!s_last) return;
    __threadfence();

    const int nact = uniform ? SPL : ((vl + TJS - 1) / TJS);
    if (tid < QT) {
        float t = 0.f;
        for (int ss = 0; ss < nact; ss++) t += g_psum[qt][ss][tid];
        s_inv[tid] = 1.f / t;
    }
    __syncthreads();

    for (int i = tid; i < QT * (DV_ / 4); i += NTH) {
        const int q = i >> 7, c = (i & 127) * 4;
        float4 a = make_float4(0.f, 0.f, 0.f, 0.f);
        for (int ss = 0; ss < nact; ss++) {
            float4 p = *(const float4*)&g_pAV[qt][ss][q][c];
            a.x += p.x; a.y += p.y; a.z += p.z; a.w += p.w;
        }
        const float inv = s_inv[q];
        *(float4*)&out[(size_t)(b * LQ_ + q0 + q) * DV_ + c] =
            make_float4(a.x * inv, a.y * inv, a.z * inv, a.w * inv);
    }
}

extern "C" void kernel_launch(void* const* d_in, const int* in_sizes, int n_in,
                              void* d_out, int out_size) {
    const float* queries = (const float*)d_in[0];
    const float* keys    = (const float*)d_in[1];
    const float* values  = (const float*)d_in[2];
    const float* Wq      = (const float*)d_in[3];
    const float* Wk      = (const float*)d_in[4];
    const float* wv      = (const float*)d_in[5];
    const int*   vlen    = (const int*)d_in[6];
    float* out = (float*)d_out;

    to_half<<<1024, 256>>>(queries, keys, Wq, Wk);
    proj_mma<<<dim3(H_ / 64, 16 + 128), 128>>>();
    reset_tick<<<1, 128>>>();                 // 3rd launch: keeps partial_attn at launch #4
    partial_attn<<<NQT * SPL, NTH>>>(values, wv, vlen, out);
}